// round 11
// baseline (speedup 1.0000x reference)
#include <cuda_runtime.h>
#include <cuda_bf16.h>
#include <math.h>

#define GG 128
#define NN 512
#define NV (GG*NN)          // 65536 nodes
#define HH 128              // hidden/feature dim
#define EHALF 8192
#define EPGP 18432          // padded directed-edge stride per graph (4-aligned segments)
#define LL 5
#define CC 10

// Scratch (device globals: allocation-free per harness rules)
__device__ float    g_bufA[NV * HH];        // 32 MB fp32 h (single buffer; kernels serialize)
__device__ unsigned g_bufH[NV * 64];        // 16 MB: h (or x) as packed bf16x2 for gather
__device__ unsigned g_Uh[NV * 64];          // 16 MB: U hi plane (bf16x2)
__device__ unsigned g_Ul[NV * 64];          // 16 MB: U lo plane (bf16x2)
__device__ int      g_row_ptr[NV];          // padded-space segment starts (4-aligned)
__device__ int      g_deg[NV];
__device__ int      g_edge_off[GG * EPGP];  // local src index * 32 (uint2-row offsets)
__device__ unsigned g_Wth[LL * HH * 64];    // W^T hi, packed bf16 k-pairs [l][n][kw]
__device__ unsigned g_Wtl[LL * HH * 64];    // W^T lo
__device__ float    g_part[GG * 8 * HH];    // readout partials

// ---------------------------------------------------------------- fused CSR build (4-aligned segments)
__global__ void __launch_bounds__(512) k_csr(const int* __restrict__ src,
                                             const int* __restrict__ dst) {
    __shared__ int cnt[NN];
    __shared__ int pos[NN];
    int g = blockIdx.x, t = threadIdx.x;
    cnt[t] = 0;
    __syncthreads();

    int base1 = g * EHALF;
    int base2 = GG * EHALF + g * EHALF;
    for (int i = t; i < EHALF; i += 512) {
        atomicAdd(&cnt[dst[base1 + i] & (NN - 1)], 1);
        atomicAdd(&cnt[dst[base2 + i] & (NN - 1)], 1);
    }
    __syncthreads();

    int c  = cnt[t];
    int p4 = (c + 3) & ~3;                 // padded count (4-aligned)
    pos[t] = p4;
    __syncthreads();
    for (int off = 1; off < NN; off <<= 1) {
        int v = (t >= off) ? pos[t - off] : 0;
        __syncthreads();
        pos[t] += v;
        __syncthreads();
    }
    int startLocal = pos[t] - p4;          // exclusive prefix (4-aligned)
    g_row_ptr[g * NN + t] = g * EPGP + startLocal;
    g_deg[g * NN + t]     = c;
    cnt[t] = startLocal;                   // local scatter cursor
    __syncthreads();

    int* eout = g_edge_off + g * EPGP;
    for (int i = t; i < EHALF; i += 512) {
        int d = dst[base1 + i] & (NN - 1);
        int p = atomicAdd(&cnt[d], 1);
        eout[p] = (src[base1 + i] & (NN - 1)) * 32;
        d = dst[base2 + i] & (NN - 1);
        p = atomicAdd(&cnt[d], 1);
        eout[p] = (src[base2 + i] & (NN - 1)) * 32;
    }
}

// ---------------------------------------------------------------- W prep: transpose + bf16 hi/lo split
__global__ void k_prepw(const float* __restrict__ W) {
    int i = blockIdx.x * blockDim.x + threadIdx.x;
    if (i >= LL * HH * 64) return;
    int kw = i & 63;
    int n  = (i >> 6) & (HH - 1);
    int l  = i >> 13;
    const float* Wl = W + l * HH * HH;
    float w0 = Wl[(2 * kw) * HH + n];
    float w1 = Wl[(2 * kw + 1) * HH + n];
    __nv_bfloat162 h = __float22bfloat162_rn(make_float2(w0, w1));
    float2 hf = __bfloat1622float2(h);
    __nv_bfloat162 lo = __float22bfloat162_rn(make_float2(w0 - hf.x, w1 - hf.y));
    g_Wth[i] = *reinterpret_cast<unsigned*>(&h);
    g_Wtl[i] = *reinterpret_cast<unsigned*>(&lo);
}

// ---------------------------------------------------------------- x -> bf16 gather copy
__global__ void __launch_bounds__(256) k_prepx(const float* __restrict__ x) {
    int i = blockIdx.x * 256 + threadIdx.x;          // NV*32 float4s
    float4 v = ((const float4*)x)[i];
    __nv_bfloat162 a = __float22bfloat162_rn(make_float2(v.x, v.y));
    __nv_bfloat162 b = __float22bfloat162_rn(make_float2(v.z, v.w));
    uint2 w;
    w.x = *(unsigned*)&a; w.y = *(unsigned*)&b;
    ((uint2*)g_bufH)[i] = w;
}

// ---------------------------------------------------------------- SpMM (all layers, bf16 gather)
// One warp per node; lane owns 4 feats. Offsets via int4 (aligned padded CSR).
// Self-term fp32 exact; output written as bf16 hi/lo planes (exact hi+lo split of acc).
__global__ void __launch_bounds__(256) k_spmm_bf(const float* __restrict__ xin,
                                                 const float* __restrict__ eps,
                                                 int layer) {
    const float* hin = (layer == 0) ? xin : g_bufA;

    int wid  = (blockIdx.x * blockDim.x + threadIdx.x) >> 5;
    int lane = threadIdx.x & 31;

    int g = wid >> 9;
    const uint2* hg2 = (const uint2*)g_bufH + (size_t)g * NN * 32;

    float e1 = 1.0f + __ldg(&eps[layer]);
    int base = wid * 32 + lane;

    float4 h0 = ((const float4*)hin)[base];
    float4 acc;
    acc.x = e1 * h0.x; acc.y = e1 * h0.y; acc.z = e1 * h0.z; acc.w = e1 * h0.w;
    float4 acc1; acc1.x = 0.f; acc1.y = 0.f; acc1.z = 0.f; acc1.w = 0.f;

    int e0 = g_row_ptr[wid];
    int d  = g_deg[wid];
    const int4* eo4 = (const int4*)(g_edge_off + e0);
    int n4 = d >> 2;

#pragma unroll 2
    for (int i = 0; i < n4; i++) {
        int4 o = eo4[i];
        uint2 v0 = hg2[o.x + lane];
        uint2 v1 = hg2[o.y + lane];
        uint2 v2 = hg2[o.z + lane];
        uint2 v3 = hg2[o.w + lane];
        acc.x  += __uint_as_float(v0.x << 16);
        acc.y  += __uint_as_float(v0.x & 0xffff0000u);
        acc.z  += __uint_as_float(v0.y << 16);
        acc.w  += __uint_as_float(v0.y & 0xffff0000u);
        acc1.x += __uint_as_float(v1.x << 16);
        acc1.y += __uint_as_float(v1.x & 0xffff0000u);
        acc1.z += __uint_as_float(v1.y << 16);
        acc1.w += __uint_as_float(v1.y & 0xffff0000u);
        acc.x  += __uint_as_float(v2.x << 16);
        acc.y  += __uint_as_float(v2.x & 0xffff0000u);
        acc.z  += __uint_as_float(v2.y << 16);
        acc.w  += __uint_as_float(v2.y & 0xffff0000u);
        acc1.x += __uint_as_float(v3.x << 16);
        acc1.y += __uint_as_float(v3.x & 0xffff0000u);
        acc1.z += __uint_as_float(v3.y << 16);
        acc1.w += __uint_as_float(v3.y & 0xffff0000u);
    }
    int rem = d & 3;
    const int* eo = g_edge_off + e0 + (n4 << 2);
    for (int i = 0; i < rem; i++) {
        uint2 v0 = hg2[eo[i] + lane];
        acc.x += __uint_as_float(v0.x << 16);
        acc.y += __uint_as_float(v0.x & 0xffff0000u);
        acc.z += __uint_as_float(v0.y << 16);
        acc.w += __uint_as_float(v0.y & 0xffff0000u);
    }
    acc.x += acc1.x; acc.y += acc1.y; acc.z += acc1.z; acc.w += acc1.w;

    // split to bf16 hi/lo planes (same arithmetic the GEMM staging used to do)
    __nv_bfloat162 hA = __float22bfloat162_rn(make_float2(acc.x, acc.y));
    __nv_bfloat162 hB = __float22bfloat162_rn(make_float2(acc.z, acc.w));
    float2 fA = __bfloat1622float2(hA);
    float2 fB = __bfloat1622float2(hB);
    __nv_bfloat162 lA = __float22bfloat162_rn(make_float2(acc.x - fA.x, acc.y - fA.y));
    __nv_bfloat162 lB = __float22bfloat162_rn(make_float2(acc.z - fB.x, acc.w - fB.y));
    uint2 hw, lw;
    hw.x = *(unsigned*)&hA; hw.y = *(unsigned*)&hB;
    lw.x = *(unsigned*)&lA; lw.y = *(unsigned*)&lB;
    ((uint2*)g_Uh)[base] = hw;
    ((uint2*)g_Ul)[base] = lw;
}

// ---------------------------------------------------------------- tensor-core GEMM + bias + relu
// h = relu(U @ W_l + b_l). 3-pass bf16 split, fp32 accum. R7 config (256 thr,
// 2x64-row tiles, warp grid 2x4, 32x32 warp tiles, ldmatrix.x4 everywhere).
// U staged by pure uint4 copy from prebuilt planes. Writes h fp32 to g_bufA
// + (optionally) bf16 copy to g_bufH via coalesced smem bounce.

#define SW 136   // bf16 elems per smem row (272 B stride, ldmatrix conflict-free)
#define SMEM_GEMM ((64*SW + 64*SW + HH*SW + HH*SW) * 2 + HH * 4)

#define MMA_BF16(C, A0, A1, A2, A3, B0, B1)                                      \
    asm volatile("mma.sync.aligned.m16n8k16.row.col.f32.bf16.bf16.f32 "          \
                 "{%0,%1,%2,%3}, {%4,%5,%6,%7}, {%8,%9}, {%0,%1,%2,%3};"         \
                 : "+f"(C[0]), "+f"(C[1]), "+f"(C[2]), "+f"(C[3])                \
                 : "r"(A0), "r"(A1), "r"(A2), "r"(A3), "r"(B0), "r"(B1))

#define LDMX4(R, addr)                                                           \
    asm volatile("ldmatrix.sync.aligned.m8n8.x4.shared.b16 {%0,%1,%2,%3}, [%4];" \
                 : "=r"(R[0]), "=r"(R[1]), "=r"(R[2]), "=r"(R[3]) : "r"(addr))

__global__ void __launch_bounds__(256) k_gemm_tc(const float* __restrict__ b,
                                                 int layer, int writeBF) {
    extern __shared__ char smem[];
    __nv_bfloat16* sUh = (__nv_bfloat16*)smem;
    __nv_bfloat16* sUl = sUh + 64 * SW;
    __nv_bfloat16* sWh = sUl + 64 * SW;
    __nv_bfloat16* sWl = sWh + HH * SW;
    float*         sB  = (float*)(sWl + HH * SW);

    int tid = threadIdx.x;

    // ---- stage W hi/lo once (packed bf16 [n][k]) ----
    {
        const uint4* wh4 = (const uint4*)(g_Wth + layer * HH * 64);
        const uint4* wl4 = (const uint4*)(g_Wtl + layer * HH * 64);
#pragma unroll
        for (int k = 0; k < 8; k++) {
            int q = tid + k * 256;            // 2048 uint4
            int n = q >> 4, cw = (q & 15) * 4;
            *(uint4*)(sWh + n * SW + cw * 2) = wh4[q];
            *(uint4*)(sWl + n * SW + cw * 2) = wl4[q];
        }
    }
    if (tid < HH) sB[tid] = b[layer * HH + tid];

    int warp = tid >> 5, lane = tid & 31;
    int wm = warp & 1, wn = warp >> 1;
    int rw = wm * 32, nw = wn * 32;

    // ldmatrix lane addressing
    int lb = lane >> 3, lr = lane & 7;
    int a_row = (lb & 1) * 8 + lr;
    int a_k   = (lb >> 1) * 8;
    int b_n   = (lb >> 1) * 8 + lr;
    int b_k   = (lb & 1) * 8;

    unsigned aH[2], aL[2], bH[2], bL[2];
#pragma unroll
    for (int mt = 0; mt < 2; mt++) {
        int row = rw + mt * 16 + a_row;
        aH[mt] = (unsigned)__cvta_generic_to_shared(sUh + row * SW + a_k);
        aL[mt] = (unsigned)__cvta_generic_to_shared(sUl + row * SW + a_k);
    }
#pragma unroll
    for (int jp = 0; jp < 2; jp++) {
        int n = nw + jp * 16 + b_n;
        bH[jp] = (unsigned)__cvta_generic_to_shared(sWh + n * SW + b_k);
        bL[jp] = (unsigned)__cvta_generic_to_shared(sWl + n * SW + b_k);
    }

    int g2 = lane >> 2, tg = lane & 3;
    unsigned* sUhU = (unsigned*)sUh;

#pragma unroll 1
    for (int tile = 0; tile < 2; tile++) {
        int rowBase = blockIdx.x * 128 + tile * 64;

        __syncthreads();   // W/bias ready (tile 0); prior copy-out done (tile 1)

        // ---- stage U: pure uint4 copy of prebuilt bf16 planes ----
        {
            const uint4* uh4 = (const uint4*)(g_Uh + (size_t)rowBase * 64);
            const uint4* ul4 = (const uint4*)(g_Ul + (size_t)rowBase * 64);
#pragma unroll
            for (int k = 0; k < 4; k++) {
                int q = tid + k * 256;        // 1024 uint4 per plane
                int r = q >> 4, c4 = q & 15;
                *(uint4*)((unsigned*)sUh + r * 68 + c4 * 4) = uh4[q];
                *(uint4*)((unsigned*)sUl + r * 68 + c4 * 4) = ul4[q];
            }
        }
        __syncthreads();

        float acc[2][4][4];
#pragma unroll
        for (int mt = 0; mt < 2; mt++)
#pragma unroll
            for (int j = 0; j < 4; j++)
#pragma unroll
                for (int q = 0; q < 4; q++) acc[mt][j][q] = 0.f;

#pragma unroll
        for (int ks = 0; ks < 8; ks++) {
            unsigned ko = (unsigned)ks * 32;  // 16 bf16 = 32 bytes
            unsigned Ah[2][4], Al[2][4];
            LDMX4(Ah[0], aH[0] + ko); LDMX4(Ah[1], aH[1] + ko);
            LDMX4(Al[0], aL[0] + ko); LDMX4(Al[1], aL[1] + ko);
#pragma unroll
            for (int jp = 0; jp < 2; jp++) {
                unsigned Bh[4], Bl[4];
                LDMX4(Bh, bH[jp] + ko);
                LDMX4(Bl, bL[jp] + ko);
#pragma unroll
                for (int mt = 0; mt < 2; mt++) {
#pragma unroll
                    for (int jj = 0; jj < 2; jj++) {
                        int j = jp * 2 + jj;
                        MMA_BF16(acc[mt][j], Ah[mt][0], Ah[mt][1], Ah[mt][2], Ah[mt][3],
                                 Bh[jj * 2], Bh[jj * 2 + 1]);
                        MMA_BF16(acc[mt][j], Al[mt][0], Al[mt][1], Al[mt][2], Al[mt][3],
                                 Bh[jj * 2], Bh[jj * 2 + 1]);
                        MMA_BF16(acc[mt][j], Ah[mt][0], Ah[mt][1], Ah[mt][2], Ah[mt][3],
                                 Bl[jj * 2], Bl[jj * 2 + 1]);
                    }
                }
            }
        }

        // ---- epilogue: bias + relu; fp32 h to g_bufA; bf16 packs kept in regs ----
        unsigned pk[2][4][2];
#pragma unroll
        for (int mt = 0; mt < 2; mt++) {
            int rA = rowBase + rw + mt * 16 + g2;
            int rB = rA + 8;
#pragma unroll
            for (int j = 0; j < 4; j++) {
                int c = nw + j * 8 + 2 * tg;
                float b0 = sB[c], b1 = sB[c + 1];
                float2 oA, oB;
                oA.x = fmaxf(acc[mt][j][0] + b0, 0.f);
                oA.y = fmaxf(acc[mt][j][1] + b1, 0.f);
                oB.x = fmaxf(acc[mt][j][2] + b0, 0.f);
                oB.y = fmaxf(acc[mt][j][3] + b1, 0.f);
                *(float2*)(g_bufA + (size_t)rA * HH + c) = oA;
                *(float2*)(g_bufA + (size_t)rB * HH + c) = oB;
                __nv_bfloat162 pA = __float22bfloat162_rn(oA);
                __nv_bfloat162 pB = __float22bfloat162_rn(oB);
                pk[mt][j][0] = *(unsigned*)&pA;
                pk[mt][j][1] = *(unsigned*)&pB;
            }
        }

        if (writeBF) {
            __syncthreads();    // all ldmatrix reads of sUh done
            // conflict-free STS: bank = (row*68 + c/2) % 32 distinct across lanes
#pragma unroll
            for (int mt = 0; mt < 2; mt++) {
                int rloc = rw + mt * 16 + g2;
#pragma unroll
                for (int j = 0; j < 4; j++) {
                    int ch = (nw >> 1) + j * 4 + tg;
                    sUhU[rloc * 68 + ch]       = pk[mt][j][0];
                    sUhU[(rloc + 8) * 68 + ch] = pk[mt][j][1];
                }
            }
            __syncthreads();
            // coalesced copy out: 1024 uint4
#pragma unroll
            for (int k = 0; k < 4; k++) {
                int q = tid + k * 256;
                int r = q >> 4, c4 = q & 15;
                ((uint4*)g_bufH)[(size_t)(rowBase + r) * 16 + c4] =
                    *(uint4*)((unsigned*)sUh + r * 68 + c4 * 4);
            }
        }
    }
}

// ---------------------------------------------------------------- readout stage 1: partial node sums
__global__ void __launch_bounds__(128) k_sum() {
    const float* h = g_bufA;
    int g = blockIdx.x >> 3, p = blockIdx.x & 7;
    int t = threadIdx.x;
    const float* base = h + (size_t)g * NN * HH + p * 64 * HH + t;
    float s0 = 0.f, s1 = 0.f;
#pragma unroll 8
    for (int r = 0; r < 64; r += 2) {
        s0 += base[r * HH];
        s1 += base[(r + 1) * HH];
    }
    g_part[(g * 8 + p) * HH + t] = s0 + s1;
}

// ---------------------------------------------------------------- readout stage 2: FCs + softmax
__global__ void __launch_bounds__(128) k_fc(const float* __restrict__ fc1w,
                                            const float* __restrict__ fc1b,
                                            const float* __restrict__ fc2w,
                                            const float* __restrict__ fc2b,
                                            float* __restrict__ out) {
    __shared__ float hg[HH];
    __shared__ float a1[HH];
    __shared__ float z[CC];
    __shared__ float ez[CC];

    int g = blockIdx.x;
    int t = threadIdx.x;

    float s = 0.f;
#pragma unroll
    for (int p = 0; p < 8; p++) s += g_part[(g * 8 + p) * HH + t];
    hg[t] = s;
    __syncthreads();

    {
        float acc = fc1b[t];
        for (int k = 0; k < HH; k++) acc += hg[k] * __ldg(&fc1w[k * HH + t]);
        a1[t] = fmaxf(acc, 0.f);
    }
    __syncthreads();

    if (t < CC) {
        float acc = fc2b[t];
        for (int k = 0; k < HH; k++) acc += a1[k] * __ldg(&fc2w[k * CC + t]);
        z[t] = acc;
    }
    __syncthreads();

    if (t < CC) {
        float m = z[0];
#pragma unroll
        for (int j = 1; j < CC; j++) m = fmaxf(m, z[j]);
        ez[t] = expf(z[t] - m);
    }
    __syncthreads();

    if (t < CC) {
        float ssum = 0.f;
#pragma unroll
        for (int j = 0; j < CC; j++) ssum += ez[j];
        out[g * CC + t] = ez[t] / ssum;
    }
}

// ---------------------------------------------------------------- launch
extern "C" void kernel_launch(void* const* d_in, const int* in_sizes, int n_in,
                              void* d_out, int out_size) {
    const float* x    = (const float*)d_in[0];
    const float* eps  = (const float*)d_in[1];
    const float* W    = (const float*)d_in[2];
    const float* b    = (const float*)d_in[3];
    const float* fc1w = (const float*)d_in[4];
    const float* fc1b = (const float*)d_in[5];
    const float* fc2w = (const float*)d_in[6];
    const float* fc2b = (const float*)d_in[7];
    const int*   src  = (const int*)d_in[8];
    const int*   dst  = (const int*)d_in[9];
    float* out = (float*)d_out;

    cudaFuncSetAttribute(k_gemm_tc, cudaFuncAttributeMaxDynamicSharedMemorySize,
                         SMEM_GEMM);

    k_csr<<<GG, 512>>>(src, dst);
    k_prepw<<<(LL * HH * 64 + 255) / 256, 256>>>(W);
    k_prepx<<<NV * 32 / 256, 256>>>(x);

    for (int l = 0; l < LL; l++) {
        k_spmm_bf<<<NV / 8, 256>>>(x, eps, l);
        k_gemm_tc<<<NV / 128, 256, SMEM_GEMM>>>(b, l, (l < LL - 1) ? 1 : 0);
    }

    k_sum<<<GG * 8, 128>>>();
    k_fc<<<GG, 128>>>(fc1w, fc1b, fc2w, fc2b, out);
}